// round 13
// baseline (speedup 1.0000x reference)
#include <cuda_runtime.h>
#include <math.h>

// ---------------- problem constants ----------------
#define FFTN     512
#define HOPW     128
#define PADW     256
#define NBANDS   80
#define BATCH    32
#define LCONST   320000
#define NFRAMES  2000
#define TFR      2501                 // STFT frames (L/HOP + 1)
#define LPAD     (LCONST + 2*PADW)    // 320512

// chunked-OLA geometry: 6 frames (3 real-pairs) per block, one pair per lane
#define CF       6                    // frames per chunk
#define CH       417                  // ceil(2501/6)
#define LANES    3                    // concurrent pairs (64 threads each)
#define NTHR     192
#define OWN      (CF*HOPW)            // 768 owned samples per chunk
#define SPILL    384                  // rightward overlap past owned range
#define SACC     (OWN + SPILL)        // 1152 samples produced per chunk
#define TWSZ     444                  // twiddle entries actually used (max idx 441)

// smem swizzle: pad every 8 float2 -> kills stride-8/64 bank conflicts
#define SW(m) ((m) + ((m) >> 3))     // max 511 -> 574 < 575

// ---------------- device scratch ----------------
__device__ float        g_ola[(size_t)BATCH * LPAD];
__device__ float        g_spill[BATCH][CH][SPILL];
__device__ float        g_window[FFTN];
__device__ float2       g_tw512[FFTN];       // W_512^m
__device__ int          g_band512[FFTN];     // mirrored bin->band+1 (0 = outside)
__device__ float        g_rdenom[LPAD];      // 1 / window^2 OLA denominator
__device__ unsigned int g_maxbits[BATCH];

// ---------------- complex helpers ----------------
__device__ __forceinline__ float2 cadd(float2 a, float2 b){ return make_float2(a.x+b.x, a.y+b.y); }
__device__ __forceinline__ float2 csub(float2 a, float2 b){ return make_float2(a.x-b.x, a.y-b.y); }
__device__ __forceinline__ float2 cmul(float2 a, float2 b){
    return make_float2(fmaf(a.x, b.x, -a.y*b.y), fmaf(a.x, b.y, a.y*b.x));
}
template<bool INV> __device__ __forceinline__ float2 rot90(float2 a){
    return INV ? make_float2(-a.y, a.x) : make_float2(a.y, -a.x);
}

// 8-point DFT in registers
template<bool INV> __device__ __forceinline__ void bfly8(float2* u){
    const float C = 0.70710678118654752440f;
    float2 s0 = cadd(u[0], u[4]), d0 = csub(u[0], u[4]);
    float2 s1 = cadd(u[2], u[6]), d1 = csub(u[2], u[6]);
    float2 E0 = cadd(s0, s1), E2 = csub(s0, s1);
    float2 r1 = rot90<INV>(d1);
    float2 E1 = cadd(d0, r1), E3 = csub(d0, r1);
    float2 t0 = cadd(u[1], u[5]), f0 = csub(u[1], u[5]);
    float2 t1 = cadd(u[3], u[7]), f1 = csub(u[3], u[7]);
    float2 O0 = cadd(t0, t1), O2 = csub(t0, t1);
    float2 r2 = rot90<INV>(f1);
    float2 O1 = cadd(f0, r2), O3 = csub(f0, r2);
    O1 = INV ? make_float2(C*(O1.x - O1.y),  C*(O1.x + O1.y))
             : make_float2(C*(O1.x + O1.y),  C*(O1.y - O1.x));
    O2 = rot90<INV>(O2);
    O3 = INV ? make_float2(-C*(O3.x + O3.y), C*(O3.x - O3.y))
             : make_float2( C*(O3.y - O3.x),-C*(O3.x + O3.y));
    u[0] = cadd(E0, O0); u[4] = csub(E0, O0);
    u[1] = cadd(E1, O1); u[5] = csub(E1, O1);
    u[2] = cadd(E2, O2); u[6] = csub(E2, O2);
    u[3] = cadd(E3, O3); u[7] = csub(E3, O3);
}

// ---------------- init: tables ----------------
__global__ void k_init(){
    int i = threadIdx.x;   // 512 threads
    double ang = 2.0 * 3.14159265358979323846 * (double)i / (double)FFTN;
    g_window[i] = (float)(0.5 * (1.0 - cos(ang)));
    double a = -2.0 * 3.14159265358979323846 * (double)i / (double)FFTN;
    g_tw512[i] = make_float2((float)cos(a), (float)sin(a));

    int f = (i <= 256) ? i : (FFTN - i);
    double mel_max = 2595.0 * log10(1.0 + 8000.0 / 700.0);
    double step = mel_max / (double)NBANDS;
    float freq = (float)f / 256.0f;
    int cnt = 0;
    for (int j = 0; j <= NBANDS; j++){
        double mel = (j == NBANDS) ? mel_max : (double)j * step;
        double hz  = 700.0 * (pow(10.0, mel / 2595.0) - 1.0);
        float  e   = (float)(hz / 8000.0);
        if (e <= freq) cnt++;           // searchsorted side='right'
    }
    int band = cnt - 1;
    g_band512[i] = (band >= 0 && band < NBANDS) ? (band + 1) : 0;
    if (i < BATCH) g_maxbits[i] = 0u;
}

// ---------------- prep: reciprocal OLA denominator ----------------
__global__ void k_prep(){
    int stride = gridDim.x * blockDim.x;
    for (int p = blockIdx.x * blockDim.x + threadIdx.x; p < LPAD; p += stride){
        float wsq = 0.0f;
        int tmax = p >> 7;
        #pragma unroll
        for (int dt = 0; dt < 4; dt++){
            int t = tmax - dt;
            if (t >= 0 && t < TFR){
                float w = g_window[p - t * HOPW];
                wsq = fmaf(w, w, wsq);
            }
        }
        g_rdenom[p] = (wsq > 1e-11f) ? (1.0f / wsq) : 1.0f;
    }
}

// ---------------- profiler-alignment no-op (3rd launch so k_frames lands 4th) ----------------
__global__ void k_nop(){}

// ---------------- chunked frames: paired real FFT -> mask -> IFFT -> sacc -> store ----------------
__global__ void __launch_bounds__(NTHR, 6)
k_frames(const float* __restrict__ mag, const float* __restrict__ noise){
    __shared__ float2 sbuf[LANES][2][575];           // 27600 B (ping-pong per lane)
    __shared__ float2 s_tw[TWSZ];                    //  3552 B
    __shared__ float  s_mb[LANES][2][NBANDS + 1];    //  1944 B
    __shared__ float  sacc[SACC];                    //  4608 B   total 37704 B -> occ 6

    const int tid = threadIdx.x;
    const int fr  = tid / 64;        // lane (pair slot) 0..2
    const int lt  = tid % 64;
    const int b   = blockIdx.y;
    const int chunk  = blockIdx.x;
    const int frame0 = chunk * CF;

    for (int i = tid; i < TWSZ; i += NTHR) s_tw[i] = g_tw512[i];
    for (int i = tid; i < SACC; i += NTHR) sacc[i] = 0.0f;

    float rwin[8]; int rband[8];
    #pragma unroll
    for (int j = 0; j < 8; j++){
        rwin[j]  = g_window[lt + 64*j];
        rband[j] = g_band512[lt + 64*j];
    }

    float2* bufA = sbuf[fr][0];
    float2* bufB = sbuf[fr][1];
    const float* np   = noise + (size_t)b * LCONST;
    const float* mrow = mag   + (size_t)b * NBANDS * NFRAMES;

    const int fA  = frame0 + 2*fr;
    const int fAc = (fA     < TFR) ? fA     : (TFR-1);
    const int fBc = (fA + 1 < TFR) ? fA + 1 : (TFR-1);
    const bool doA = (fA     < TFR);
    const bool doB = (fA + 1 < TFR);

    // per-pair interpolated band magnitudes (both frames)
    #pragma unroll
    for (int half = 0; half < 2; half++){
        int t = half ? fBc : fAc;
        double pos = (double)t * ((double)(NFRAMES-1)/(double)(TFR-1));
        int i0 = (int)pos;
        int i1 = (i0 + 1 < NFRAMES) ? (i0 + 1) : (NFRAMES - 1);
        float w = (float)(pos - (double)i0);
        for (int band = lt; band < NBANDS; band += 64){
            const float* row = mrow + (size_t)band * NFRAMES;
            s_mb[fr][half][band + 1] = fmaf(row[i1] - row[i0], w, row[i0]);
        }
        if (lt == 0) s_mb[fr][half][0] = 0.0f;
    }
    __syncthreads();   // S0: masks + sacc zero + twiddles ready

    // ---- load pair (A->re, B->im) + forward stage 1 -> bufA ----
    float2 u[8];
    const int baseA = fAc * HOPW, baseB = fBc * HOPW;
    #pragma unroll
    for (int j = 0; j < 8; j++){
        int idx = lt + 64*j;
        int qa = baseA + idx - PADW;
        qa = (qa < 0) ? -qa : qa;
        qa = (qa >= LCONST) ? (2*(LCONST-1) - qa) : qa;
        int qb = baseB + idx - PADW;
        qb = (qb < 0) ? -qb : qb;
        qb = (qb >= LCONST) ? (2*(LCONST-1) - qb) : qb;
        u[j] = make_float2(np[qa] * rwin[j], np[qb] * rwin[j]);
    }
    bfly8<false>(u);
    #pragma unroll
    for (int i = 0; i < 8; i++) bufA[SW(8*lt + i)] = u[i];
    __syncthreads();   // S1

    // ---- forward stage 2: bufA -> bufB ----
    {
        const int k = lt & 7;
        #pragma unroll
        for (int j = 0; j < 8; j++)
            u[j] = cmul(bufA[SW(lt + 64*j)], s_tw[j * k * 8]);
        bfly8<false>(u);
        const int ob = (lt & ~7) * 8 + k;
        #pragma unroll
        for (int i = 0; i < 8; i++) bufB[SW(ob + i*8)] = u[i];
    }
    __syncthreads();   // S2

    // ---- forward stage 3: bufB -> Z in regs, also store natural-order Z to bufA ----
    #pragma unroll
    for (int j = 0; j < 8; j++)
        u[j] = cmul(bufB[SW(lt + 64*j)], s_tw[j * lt]);
    bfly8<false>(u);
    #pragma unroll
    for (int i = 0; i < 8; i++) bufA[SW(lt + 64*i)] = u[i];   // Z natural (for mirror)
    __syncthreads();   // S3

    // ---- pair-split + mask + recombine (own Z from regs, mirror from bufA) + inv stage 1 -> bufB ----
    // Z'(m) = (mA+mB)*Z(m) + (mA-mB)*conj(Z(512-m))   (x1/2 folded into scale)
    #pragma unroll
    for (int j = 0; j < 8; j++){
        int m = lt + 64*j;
        float2 Zm = bufA[SW((FFTN - m) & (FFTN - 1))];
        float mA = s_mb[fr][0][rband[j]];
        float mB = s_mb[fr][1][rband[j]];
        float sp = mA + mB, sm = mA - mB;
        u[j] = make_float2(fmaf(sp, u[j].x,  sm * Zm.x),
                           fmaf(sp, u[j].y, -sm * Zm.y));
    }
    bfly8<true>(u);
    #pragma unroll
    for (int i = 0; i < 8; i++) bufB[SW(8*lt + i)] = u[i];
    __syncthreads();   // S4: mirror reads done, inv1 data ready

    // ---- inverse stage 2: bufB -> bufA ----
    {
        const int k = lt & 7;
        #pragma unroll
        for (int j = 0; j < 8; j++){
            float2 w = s_tw[j * k * 8]; w.y = -w.y;
            u[j] = cmul(bufB[SW(lt + 64*j)], w);
        }
        bfly8<true>(u);
        const int ob = (lt & ~7) * 8 + k;
        #pragma unroll
        for (int i = 0; i < 8; i++) bufA[SW(ob + i*8)] = u[i];
    }
    __syncthreads();   // S5

    // ---- inverse stage 3: bufA -> registers; Re->frame A, Im->frame B ----
    #pragma unroll
    for (int j = 0; j < 8; j++){
        float2 w = s_tw[j * lt]; w.y = -w.y;
        u[j] = cmul(bufA[SW(lt + 64*j)], w);
    }
    bfly8<true>(u);

    // ---- window + smem OLA (atomics; proven cheap in R8) ----
    const float scale = 1.0f / (2.0f * (float)FFTN);   // 1/2 (pair) * 1/N (ifft)
    const int posA = 2*fr*HOPW;
    #pragma unroll
    for (int i = 0; i < 8; i++){
        int idx = lt + 64*i;
        float wv = rwin[i] * scale;
        if (doA) atomicAdd(&sacc[posA + idx],        u[i].x * wv);
        if (doB) atomicAdd(&sacc[posA + HOPW + idx], u[i].y * wv);
    }
    __syncthreads();   // S6: sacc complete

    // ---- write owned range (plain stores) + spill ----
    const bool lastc = (chunk == CH - 1);
    const int own_start = frame0 * HOPW;
    const int own_len   = lastc ? (LPAD - own_start) : OWN;
    float* ola = g_ola + (size_t)b * LPAD + own_start;
    for (int s = tid; s < SACC; s += NTHR){
        float acc = sacc[s];
        if (s < own_len)                 ola[s] = acc;
        else if (!lastc && s >= OWN)     g_spill[b][chunk][s - OWN] = acc;
    }
}

// ---------------- per-batch max |y| (ola + spill merge) ----------------
__global__ void __launch_bounds__(256) k_max(){
    const int b = blockIdx.y;
    const float4* ola4 = (const float4*)(g_ola + (size_t)b * LPAD + PADW);
    const float4* rd4  = (const float4*)(g_rdenom + PADW);
    float mx = 0.0f;
    int stride = gridDim.x * blockDim.x;
    for (int i = blockIdx.x * blockDim.x + threadIdx.x; i < LCONST / 4; i += stride){
        int gp = PADW + 4*i;
        int ck = gp / OWN;
        int off = gp - ck * OWN;
        float4 a = ola4[i];
        if (ck > 0 && off < SPILL){
            const float4 s = *(const float4*)&g_spill[b][ck - 1][off];
            a.x += s.x; a.y += s.y; a.z += s.z; a.w += s.w;
        }
        float4 r = rd4[i];
        float m0 = fmaxf(fabsf(a.x * r.x), fabsf(a.y * r.y));
        float m1 = fmaxf(fabsf(a.z * r.z), fabsf(a.w * r.w));
        mx = fmaxf(mx, fmaxf(m0, m1));
    }
    #pragma unroll
    for (int o = 16; o; o >>= 1) mx = fmaxf(mx, __shfl_xor_sync(0xffffffffu, mx, o));
    __shared__ float red[8];
    if ((threadIdx.x & 31) == 0) red[threadIdx.x >> 5] = mx;
    __syncthreads();
    if (threadIdx.x == 0){
        float m2 = red[0];
        #pragma unroll
        for (int w = 1; w < 8; w++) m2 = fmaxf(m2, red[w]);
        atomicMax(&g_maxbits[b], __float_as_uint(m2));
    }
}

// ---------------- normalized output ----------------
__global__ void __launch_bounds__(256) k_out(float* __restrict__ out){
    const int b = blockIdx.y;
    const float4* ola4 = (const float4*)(g_ola + (size_t)b * LPAD + PADW);
    const float4* rd4  = (const float4*)(g_rdenom + PADW);
    float4* o = (float4*)(out + (size_t)b * LCONST);
    const float inv = 1.0f / (__uint_as_float(g_maxbits[b]) + 1e-8f);
    int stride = gridDim.x * blockDim.x;
    for (int i = blockIdx.x * blockDim.x + threadIdx.x; i < LCONST / 4; i += stride){
        int gp = PADW + 4*i;
        int ck = gp / OWN;
        int off = gp - ck * OWN;
        float4 a = ola4[i];
        if (ck > 0 && off < SPILL){
            const float4 s = *(const float4*)&g_spill[b][ck - 1][off];
            a.x += s.x; a.y += s.y; a.z += s.z; a.w += s.w;
        }
        float4 r = rd4[i];
        o[i] = make_float4(a.x * r.x * inv, a.y * r.y * inv,
                           a.z * r.z * inv, a.w * r.w * inv);
    }
}

// ---------------- launch ----------------
extern "C" void kernel_launch(void* const* d_in, const int* in_sizes, int n_in,
                              void* d_out, int out_size) {
    const float* mag   = (const float*)d_in[0];   // [32, 80, 2000]
    const float* noise = (const float*)d_in[1];   // [32, 320000]
    float* out = (float*)d_out;                   // [32, 320000]
    (void)in_sizes; (void)n_in; (void)out_size;

    k_init<<<1, 512>>>();
    k_prep<<<160, 256>>>();
    k_nop<<<1, 32>>>();                            // shifts k_frames into capture slot 4
    k_frames<<<dim3(CH, BATCH), NTHR>>>(mag, noise);
    k_max<<<dim3(64, BATCH), 256>>>();
    k_out<<<dim3(64, BATCH), 256>>>(out);
}